// round 4
// baseline (speedup 1.0000x reference)
#include <cuda_runtime.h>
#include <cuda_fp16.h>
#include <cstdint>

// ============================================================================
// Problem constants (dataset: n1=n2=8192, d=256)
// ============================================================================
#define D_DIM 256
#define N_MAX 8192
#define SQRT3F 1.7320508075688772f

// Scratch (allocation-free rule: __device__ globals)
__device__ __align__(128) __half g_ah[N_MAX * D_DIM];
__device__ __align__(128) __half g_al[N_MAX * D_DIM];
__device__ __align__(128) __half g_bh[N_MAX * D_DIM];
__device__ __align__(128) __half g_bl[N_MAX * D_DIM];
__device__ __align__(128) float  g_sq1[N_MAX];
__device__ __align__(128) float  g_sq2[N_MAX];
__device__ __align__(128) float  g_part[32 * D_DIM];
__device__ __align__(128) float  g_adj[D_DIM];
__device__ __align__(128) float  g_rls[D_DIM];

// ============================================================================
// Bit-cast helpers (no such intrinsics exist; aliasing is free in SASS)
// ============================================================================
__device__ __forceinline__ uint32_t h2_to_u32(__half2 h) {
    union { __half2 h; uint32_t u; } c; c.h = h; return c.u;
}
__device__ __forceinline__ __half2 u32_to_h2(uint32_t u) {
    union { uint32_t u; __half2 h; } c; c.u = u; return c.h;
}

// ============================================================================
// Portable PTX helpers (sm_80-era ISA only: cp.async / ldmatrix / mma.sync)
// ============================================================================
__device__ __forceinline__ uint32_t smem_u32(const void* p) {
    uint32_t a;
    asm("{ .reg .u64 t; cvta.to.shared.u64 t, %1; cvt.u32.u64 %0, t; }"
        : "=r"(a) : "l"(p));
    return a;
}

__device__ __forceinline__ void cp16(uint32_t dst, const void* src) {
    asm volatile("cp.async.cg.shared.global [%0], [%1], 16;"
                 :: "r"(dst), "l"(src) : "memory");
}
#define CP_COMMIT() asm volatile("cp.async.commit_group;" ::: "memory")
#define CP_WAIT1()  asm volatile("cp.async.wait_group 1;" ::: "memory")

#define LDSM_X4(r, addr) \
    asm volatile("ldmatrix.sync.aligned.m8n8.x4.shared.b16 {%0,%1,%2,%3}, [%4];" \
                 : "=r"((r)[0]), "=r"((r)[1]), "=r"((r)[2]), "=r"((r)[3]) \
                 : "r"(addr))

// fp32-accumulator HMMA (main hh pass)
__device__ __forceinline__ void mma16816_f32(float* c, const uint32_t* a,
                                             const uint32_t* b) {
    asm volatile(
        "mma.sync.aligned.m16n8k16.row.col.f32.f16.f16.f32 "
        "{%0,%1,%2,%3}, {%4,%5,%6,%7}, {%8,%9}, {%0,%1,%2,%3};"
        : "+f"(c[0]), "+f"(c[1]), "+f"(c[2]), "+f"(c[3])
        : "r"(a[0]), "r"(a[1]), "r"(a[2]), "r"(a[3]),
          "r"(b[0]), "r"(b[1]));
}

// fp16-accumulator HMMA (small cross terms ah*bl + al*bh; 2x rate)
__device__ __forceinline__ void mma16816_f16(uint32_t* c, const uint32_t* a,
                                             const uint32_t* b) {
    asm volatile(
        "mma.sync.aligned.m16n8k16.row.col.f16.f16.f16.f16 "
        "{%0,%1}, {%2,%3,%4,%5}, {%6,%7}, {%0,%1};"
        : "+r"(c[0]), "+r"(c[1])
        : "r"(a[0]), "r"(a[1]), "r"(a[2]), "r"(a[3]),
          "r"(b[0]), "r"(b[1]));
}

// ============================================================================
// Prep kernels
// ============================================================================
__global__ void k_mean_partial(const float* __restrict__ x1, int n1) {
    int d = threadIdx.x, b = blockIdx.x;
    float s = 0.f;
    for (int r = b; r < n1; r += 32) s += x1[(size_t)r * D_DIM + d];
    g_part[b * D_DIM + d] = s;
}

__global__ void k_mean_final(const float* __restrict__ ls, int n1) {
    int d = threadIdx.x;
    float s = 0.f;
#pragma unroll
    for (int b = 0; b < 32; b++) s += g_part[b * D_DIM + d];
    g_adj[d] = s / (float)n1;
    g_rls[d] = 1.0f / ls[d];     // exact divide, once
}

// Center, scale, split fp32 -> fp16 hi + lo; row sqnorm. One warp per row,
// float4 loads, uint4 (8 x fp16) stores, shfl reduce.
__global__ void k_normalize2(const float* __restrict__ x, int which, int n) {
    int wid  = threadIdx.x >> 5;
    int lane = threadIdx.x & 31;
    int row  = blockIdx.x * 8 + wid;
    if (row >= n) return;

    __half* hi = which ? g_bh : g_ah;
    __half* lo = which ? g_bl : g_al;
    float*  sq = which ? g_sq2 : g_sq1;

    const float4* xr = reinterpret_cast<const float4*>(x + (size_t)row * D_DIM);
    const float4* aj = reinterpret_cast<const float4*>(g_adj);
    const float4* rl = reinterpret_cast<const float4*>(g_rls);

    float ssum = 0.f;
    uint4 packh, packl;
    uint32_t* ph = reinterpret_cast<uint32_t*>(&packh);
    uint32_t* pl = reinterpret_cast<uint32_t*>(&packl);
#pragma unroll
    for (int g = 0; g < 2; g++) {
        int v4 = lane * 2 + g;                 // float4 index 0..63
        float4 xv = xr[v4];
        float4 av = aj[v4];
        float4 rv = rl[v4];
        float vv[4] = { (xv.x - av.x) * rv.x, (xv.y - av.y) * rv.y,
                        (xv.z - av.z) * rv.z, (xv.w - av.w) * rv.w };
#pragma unroll
        for (int e = 0; e < 4; e += 2) {
            __half h0 = __float2half_rn(vv[e]);
            __half h1 = __float2half_rn(vv[e + 1]);
            __half l0 = __float2half_rn(vv[e] - __half2float(h0));
            __half l1 = __float2half_rn(vv[e + 1] - __half2float(h1));
            ph[g * 2 + e / 2] = h2_to_u32(__halves2half2(h0, h1));
            pl[g * 2 + e / 2] = h2_to_u32(__halves2half2(l0, l1));
            float r0 = __half2float(h0) + __half2float(l0);
            float r1 = __half2float(h1) + __half2float(l1);
            ssum = fmaf(r0, r0, ssum);
            ssum = fmaf(r1, r1, ssum);
        }
    }
    // store 8 halves = 16B per thread, coalesced
    reinterpret_cast<uint4*>(hi + (size_t)row * D_DIM)[lane] = packh;
    reinterpret_cast<uint4*>(lo + (size_t)row * D_DIM)[lane] = packl;
#pragma unroll
    for (int o = 16; o > 0; o >>= 1)
        ssum += __shfl_xor_sync(0xffffffffu, ssum, o);
    if (lane == 0) sq[row] = ssum;
}

// ============================================================================
// Fused GEMM + Matern epilogue (mma.sync m16n8k16, fp16 hi/lo split)
//
// CTA tile 128x128, 8 warps in 2x4 grid, warp tile 64x32.
// K = 256 in 8 chunks of 32, cp.async double-buffered.
// Smem rows padded to 80B -> conflict-free ldmatrix (gcd(5,8)=1 permutation).
// Per k16 step: hh pass in fp32 accum; (ah*bl + al*bh) merged in fp16 accum.
// ============================================================================
#define ROW_B    80                    // padded row stride
#define TILE_B   (128 * ROW_B)         // 10240 B per tile
#define STAGE_B  (4 * TILE_B)          // Ah | Al | Bh | Bl
#define SMEM_REQ (2 * STAGE_B + 1536)

__global__ void __launch_bounds__(256, 1)
k_matern_gemm(float* __restrict__ out, int n2) {
    extern __shared__ char smem_raw[];
    uint32_t sbase_u = smem_u32(smem_raw);
    uint32_t abase = (sbase_u + 127u) & ~127u;
    char* ap = smem_raw + (abase - sbase_u);

    const int tid  = threadIdx.x;
    const int lane = tid & 31;
    const int wid  = tid >> 5;
    const int wm   = wid >> 2;   // 0..1 : 64-row slice
    const int wn   = wid & 3;    // 0..3 : 32-col slice
    const int bX   = blockIdx.x;
    const int bY   = blockIdx.y;

    float* s_sq1 = reinterpret_cast<float*>(ap + 2 * STAGE_B);
    float* s_sq2 = reinterpret_cast<float*>(ap + 2 * STAGE_B + 512);
    if (tid < 128) {
        s_sq1[tid] = g_sq1[(size_t)bY * 128 + tid];
        s_sq2[tid] = g_sq2[(size_t)bX * 128 + tid];
    }

    const __half* __restrict__ pAh = g_ah + (size_t)bY * 128 * D_DIM;
    const __half* __restrict__ pAl = g_al + (size_t)bY * 128 * D_DIM;
    const __half* __restrict__ pBh = g_bh + (size_t)bX * 128 * D_DIM;
    const __half* __restrict__ pBl = g_bl + (size_t)bX * 128 * D_DIM;

    auto load_stage = [&](int buf, int kc) {
        uint32_t sbuf = abase + (uint32_t)buf * STAGE_B;
        const __half* srcs[4] = { pAh, pAl, pBh, pBl };
#pragma unroll
        for (int t4 = 0; t4 < 4; t4++) {
            const __half* src = srcs[t4];
#pragma unroll
            for (int i = 0; i < 2; i++) {
                int idx = tid + i * 256;            // 0..511
                int row = idx >> 2;                 // 0..127
                int g   = idx & 3;                  // 16B group
                uint32_t daddr = sbuf + (uint32_t)t4 * TILE_B
                               + (uint32_t)(row * ROW_B + g * 16);
                cp16(daddr, src + (size_t)row * D_DIM + kc * 32 + g * 8);
            }
        }
    };

    float acc[4][4][4];                 // hh, fp32
    uint32_t accx[4][4][2];             // cross, fp16x2
#pragma unroll
    for (int i = 0; i < 4; i++)
#pragma unroll
        for (int j = 0; j < 4; j++) {
#pragma unroll
            for (int e = 0; e < 4; e++) acc[i][j][e] = 0.f;
            accx[i][j][0] = 0u; accx[i][j][1] = 0u;
        }

    load_stage(0, 0);
    CP_COMMIT();

    const int NCHUNK = D_DIM / 32;   // 8
    for (int c = 0; c < NCHUNK; c++) {
        if (c + 1 < NCHUNK) load_stage((c + 1) & 1, c + 1);
        CP_COMMIT();
        CP_WAIT1();
        __syncthreads();

        uint32_t sA = abase + (uint32_t)(c & 1) * STAGE_B;
        uint32_t sB = sA + 2 * TILE_B;

#pragma unroll
        for (int s = 0; s < 2; s++) {            // two k16 steps per 32-chunk
            uint32_t ah[4][4], al[4][4];
            int arow = wm * 64 + (lane & 15);
            int ag   = s * 2 + (lane >> 4);
#pragma unroll
            for (int mt = 0; mt < 4; mt++) {
                uint32_t aaddr = sA + (uint32_t)((arow + mt * 16) * ROW_B + ag * 16);
                LDSM_X4(ah[mt], aaddr);
                LDSM_X4(al[mt], aaddr + TILE_B);
            }
            int t  = lane >> 3;
            int bn = wn * 32 + ((t >> 1) << 3) + (lane & 7);
            int bg = s * 2 + (t & 1);
#pragma unroll
            for (int nt2 = 0; nt2 < 2; nt2++) {
                uint32_t baddr = sB + (uint32_t)((bn + nt2 * 16) * ROW_B + bg * 16);
                uint32_t bh[4], bl[4];
                LDSM_X4(bh, baddr);
                LDSM_X4(bl, baddr + TILE_B);
#pragma unroll
                for (int mt = 0; mt < 4; mt++) {
                    // main: fp32 accum
                    mma16816_f32(acc[mt][nt2 * 2],     ah[mt], bh);
                    mma16816_f32(acc[mt][nt2 * 2 + 1], ah[mt], bh + 2);
                    // cross: merged fp16 accum (values ~1e-2, no overflow)
                    mma16816_f16(accx[mt][nt2 * 2],     ah[mt], bl);
                    mma16816_f16(accx[mt][nt2 * 2],     al[mt], bh);
                    mma16816_f16(accx[mt][nt2 * 2 + 1], ah[mt], bl + 2);
                    mma16816_f16(accx[mt][nt2 * 2 + 1], al[mt], bh + 2);
                }
            }
        }
        __syncthreads();
    }

    // ---- fused Matern epilogue ----
    const int r0 = lane >> 2;
    const int c0 = 2 * (lane & 3);
#pragma unroll
    for (int mt = 0; mt < 4; mt++) {
        int row_l = wm * 64 + mt * 16 + r0;
        int row_g = bY * 128 + row_l;
        float sqa0 = s_sq1[row_l];
        float sqa8 = s_sq1[row_l + 8];
        float* orow0 = out + (size_t)row_g * (size_t)n2 + (size_t)bX * 128;
        float* orow8 = orow0 + 8u * (size_t)n2;
#pragma unroll
        for (int nt = 0; nt < 4; nt++) {
            int col_l = wn * 32 + nt * 8 + c0;
            float sqb0 = s_sq2[col_l];
            float sqb1 = s_sq2[col_l + 1];
            const float* a = acc[mt][nt];
            float2 x0 = __half22float2(u32_to_h2(accx[mt][nt][0]));
            float2 x1 = __half22float2(u32_to_h2(accx[mt][nt][1]));
            float dots[4] = { a[0] + x0.x, a[1] + x0.y, a[2] + x1.x, a[3] + x1.y };
            float sqs[4]  = { sqa0 + sqb0, sqa0 + sqb1, sqa8 + sqb0, sqa8 + sqb1 };
            float res[4];
#pragma unroll
            for (int e = 0; e < 4; e++) {
                float d2 = fmaf(-2.f, dots[e], sqs[e]);
                d2 = fmaxf(d2, 1e-30f);
                float t = SQRT3F * (d2 * rsqrtf(d2));
                res[e] = (1.f + t) * __expf(-t);
            }
            *reinterpret_cast<float2*>(orow0 + col_l) = make_float2(res[0], res[1]);
            *reinterpret_cast<float2*>(orow8 + col_l) = make_float2(res[2], res[3]);
        }
    }
}

// ============================================================================
// kernel_launch
// ============================================================================
extern "C" void kernel_launch(void* const* d_in, const int* in_sizes, int n_in,
                              void* d_out, int out_size) {
    const float* x1 = (const float*)d_in[0];
    const float* x2 = (const float*)d_in[1];
    const float* ls = (const float*)d_in[2];
    float* out = (float*)d_out;

    int d  = in_sizes[2];            // 256
    int n1 = in_sizes[0] / d;        // 8192
    int n2 = in_sizes[1] / d;        // 8192

    k_mean_partial<<<32, D_DIM>>>(x1, n1);
    k_mean_final<<<1, D_DIM>>>(ls, n1);
    k_normalize2<<<n1 / 8, 256>>>(x1, 0, n1);
    k_normalize2<<<n2 / 8, 256>>>(x2, 1, n2);

    static bool attr_set = false;
    if (!attr_set) {
        cudaFuncSetAttribute(k_matern_gemm,
                             cudaFuncAttributeMaxDynamicSharedMemorySize, SMEM_REQ);
        attr_set = true;
    }
    dim3 grid(n2 / 128, n1 / 128);
    k_matern_gemm<<<grid, 256, SMEM_REQ>>>(out, n2);
}

// round 5
// speedup vs baseline: 1.2277x; 1.2277x over previous
#include <cuda_runtime.h>
#include <cuda_fp16.h>
#include <cstdint>

// ============================================================================
// Problem constants (dataset: n1=n2=8192, d=256)
// ============================================================================
#define D_DIM 256
#define N_MAX 8192
#define SQRT3F 1.7320508075688772f

// Scratch (allocation-free rule: __device__ globals)
__device__ __align__(128) __half g_ah[N_MAX * D_DIM];
__device__ __align__(128) __half g_al[N_MAX * D_DIM];
__device__ __align__(128) __half g_bh[N_MAX * D_DIM];
__device__ __align__(128) __half g_bl[N_MAX * D_DIM];
__device__ __align__(128) float  g_sq1[N_MAX];
__device__ __align__(128) float  g_sq2[N_MAX];
__device__ __align__(128) float  g_part[32 * D_DIM];
__device__ __align__(128) float  g_adj[D_DIM];
__device__ __align__(128) float  g_rls[D_DIM];

__device__ __forceinline__ uint32_t h2_to_u32(__half2 h) {
    union { __half2 h; uint32_t u; } c; c.h = h; return c.u;
}

// ============================================================================
// Portable PTX helpers (sm_80-era ISA only: cp.async / ldmatrix / mma.sync)
// ============================================================================
__device__ __forceinline__ uint32_t smem_u32(const void* p) {
    uint32_t a;
    asm("{ .reg .u64 t; cvta.to.shared.u64 t, %1; cvt.u32.u64 %0, t; }"
        : "=r"(a) : "l"(p));
    return a;
}

__device__ __forceinline__ void cp16(uint32_t dst, const void* src) {
    asm volatile("cp.async.cg.shared.global [%0], [%1], 16;"
                 :: "r"(dst), "l"(src) : "memory");
}
#define CP_COMMIT() asm volatile("cp.async.commit_group;" ::: "memory")
#define CP_WAIT1()  asm volatile("cp.async.wait_group 1;" ::: "memory")

#define LDSM_X4(r, addr) \
    asm volatile("ldmatrix.sync.aligned.m8n8.x4.shared.b16 {%0,%1,%2,%3}, [%4];" \
                 : "=r"((r)[0]), "=r"((r)[1]), "=r"((r)[2]), "=r"((r)[3]) \
                 : "r"(addr))

// fp32-accumulator HMMA
__device__ __forceinline__ void mma16816_f32(float* c, const uint32_t* a,
                                             const uint32_t* b) {
    asm volatile(
        "mma.sync.aligned.m16n8k16.row.col.f32.f16.f16.f32 "
        "{%0,%1,%2,%3}, {%4,%5,%6,%7}, {%8,%9}, {%0,%1,%2,%3};"
        : "+f"(c[0]), "+f"(c[1]), "+f"(c[2]), "+f"(c[3])
        : "r"(a[0]), "r"(a[1]), "r"(a[2]), "r"(a[3]),
          "r"(b[0]), "r"(b[1]));
}

// ============================================================================
// Prep kernels
// ============================================================================
__global__ void k_mean_partial(const float* __restrict__ x1, int n1) {
    int d = threadIdx.x, b = blockIdx.x;
    float s = 0.f;
    for (int r = b; r < n1; r += 32) s += x1[(size_t)r * D_DIM + d];
    g_part[b * D_DIM + d] = s;
}

__global__ void k_mean_final(const float* __restrict__ ls, int n1) {
    int d = threadIdx.x;
    float s = 0.f;
#pragma unroll
    for (int b = 0; b < 32; b++) s += g_part[b * D_DIM + d];
    g_adj[d] = s / (float)n1;
    g_rls[d] = 1.0f / ls[d];     // exact divide, once
}

// Center, scale, split fp32 -> fp16 hi + lo; row sqnorm. One warp per row.
__global__ void k_normalize2(const float* __restrict__ x, int which, int n) {
    int wid  = threadIdx.x >> 5;
    int lane = threadIdx.x & 31;
    int row  = blockIdx.x * 8 + wid;
    if (row >= n) return;

    __half* hi = which ? g_bh : g_ah;
    __half* lo = which ? g_bl : g_al;
    float*  sq = which ? g_sq2 : g_sq1;

    const float4* xr = reinterpret_cast<const float4*>(x + (size_t)row * D_DIM);
    const float4* aj = reinterpret_cast<const float4*>(g_adj);
    const float4* rl = reinterpret_cast<const float4*>(g_rls);

    float ssum = 0.f;
    uint4 packh, packl;
    uint32_t* ph = reinterpret_cast<uint32_t*>(&packh);
    uint32_t* pl = reinterpret_cast<uint32_t*>(&packl);
#pragma unroll
    for (int g = 0; g < 2; g++) {
        int v4 = lane * 2 + g;
        float4 xv = xr[v4];
        float4 av = aj[v4];
        float4 rv = rl[v4];
        float vv[4] = { (xv.x - av.x) * rv.x, (xv.y - av.y) * rv.y,
                        (xv.z - av.z) * rv.z, (xv.w - av.w) * rv.w };
#pragma unroll
        for (int e = 0; e < 4; e += 2) {
            __half h0 = __float2half_rn(vv[e]);
            __half h1 = __float2half_rn(vv[e + 1]);
            __half l0 = __float2half_rn(vv[e] - __half2float(h0));
            __half l1 = __float2half_rn(vv[e + 1] - __half2float(h1));
            ph[g * 2 + e / 2] = h2_to_u32(__halves2half2(h0, h1));
            pl[g * 2 + e / 2] = h2_to_u32(__halves2half2(l0, l1));
            float r0 = __half2float(h0) + __half2float(l0);
            float r1 = __half2float(h1) + __half2float(l1);
            ssum = fmaf(r0, r0, ssum);
            ssum = fmaf(r1, r1, ssum);
        }
    }
    reinterpret_cast<uint4*>(hi + (size_t)row * D_DIM)[lane] = packh;
    reinterpret_cast<uint4*>(lo + (size_t)row * D_DIM)[lane] = packl;
#pragma unroll
    for (int o = 16; o > 0; o >>= 1)
        ssum += __shfl_xor_sync(0xffffffffu, ssum, o);
    if (lane == 0) sq[row] = ssum;
}

// Tiny spacer so the GEMM is the 6th launch -> ncu (-s 5 -c 1) profiles it.
__global__ void k_spacer() {}

// ============================================================================
// Fused GEMM + Matern epilogue (mma.sync m16n8k16, fp16 hi/lo split)
//
// CTA tile 128x128, 8 warps (2x4), warp tile 64x32, occ 2.
// K = 256 in 8 chunks of 32, cp.async double-buffered.
// Per k16 step: 48 MMAs issued in 3 passes (hh / ah*bl / al*bh) so that
// consecutive MMAs always hit DIFFERENT accumulators (reuse distance 16).
// ============================================================================
#define ROW_B    80                    // padded row stride
#define TILE_B   (128 * ROW_B)         // 10240 B per tile
#define STAGE_B  (4 * TILE_B)          // Ah | Al | Bh | Bl
#define SMEM_REQ (2 * STAGE_B + 1536)

__global__ void __launch_bounds__(256, 2)
k_matern_gemm(float* __restrict__ out, int n2) {
    extern __shared__ char smem_raw[];
    uint32_t sbase_u = smem_u32(smem_raw);
    uint32_t abase = (sbase_u + 127u) & ~127u;
    char* ap = smem_raw + (abase - sbase_u);

    const int tid  = threadIdx.x;
    const int lane = tid & 31;
    const int wid  = tid >> 5;
    const int wm   = wid >> 2;   // 0..1 : 64-row slice
    const int wn   = wid & 3;    // 0..3 : 32-col slice
    const int bX   = blockIdx.x;
    const int bY   = blockIdx.y;

    float* s_sq1 = reinterpret_cast<float*>(ap + 2 * STAGE_B);
    float* s_sq2 = reinterpret_cast<float*>(ap + 2 * STAGE_B + 512);
    if (tid < 128) {
        s_sq1[tid] = g_sq1[(size_t)bY * 128 + tid];
        s_sq2[tid] = g_sq2[(size_t)bX * 128 + tid];
    }

    const __half* __restrict__ pAh = g_ah + (size_t)bY * 128 * D_DIM;
    const __half* __restrict__ pAl = g_al + (size_t)bY * 128 * D_DIM;
    const __half* __restrict__ pBh = g_bh + (size_t)bX * 128 * D_DIM;
    const __half* __restrict__ pBl = g_bl + (size_t)bX * 128 * D_DIM;

    auto load_stage = [&](int buf, int kc) {
        uint32_t sbuf = abase + (uint32_t)buf * STAGE_B;
        const __half* srcs[4] = { pAh, pAl, pBh, pBl };
#pragma unroll
        for (int t4 = 0; t4 < 4; t4++) {
            const __half* src = srcs[t4];
#pragma unroll
            for (int i = 0; i < 2; i++) {
                int idx = tid + i * 256;            // 0..511
                int row = idx >> 2;                 // 0..127
                int g   = idx & 3;                  // 16B group
                uint32_t daddr = sbuf + (uint32_t)t4 * TILE_B
                               + (uint32_t)(row * ROW_B + g * 16);
                cp16(daddr, src + (size_t)row * D_DIM + kc * 32 + g * 8);
            }
        }
    };

    float acc[4][4][4];                 // [mt][n-col][4], all fp32
#pragma unroll
    for (int i = 0; i < 4; i++)
#pragma unroll
        for (int j = 0; j < 4; j++)
#pragma unroll
            for (int e = 0; e < 4; e++) acc[i][j][e] = 0.f;

    load_stage(0, 0);
    CP_COMMIT();

    const int NCHUNK = D_DIM / 32;   // 8
    for (int c = 0; c < NCHUNK; c++) {
        if (c + 1 < NCHUNK) load_stage((c + 1) & 1, c + 1);
        CP_COMMIT();
        CP_WAIT1();
        __syncthreads();

        uint32_t sA = abase + (uint32_t)(c & 1) * STAGE_B;
        uint32_t sB = sA + 2 * TILE_B;

#pragma unroll
        for (int s = 0; s < 2; s++) {            // two k16 steps per 32-chunk
            // ---- load ALL fragments first ----
            uint32_t ah[4][4], al[4][4], bh[2][4], bl[2][4];
            int arow = wm * 64 + (lane & 15);
            int ag   = s * 2 + (lane >> 4);
#pragma unroll
            for (int mt = 0; mt < 4; mt++) {
                uint32_t aaddr = sA + (uint32_t)((arow + mt * 16) * ROW_B + ag * 16);
                LDSM_X4(ah[mt], aaddr);
                LDSM_X4(al[mt], aaddr + TILE_B);
            }
            int t  = lane >> 3;
            int bn = wn * 32 + ((t >> 1) << 3) + (lane & 7);
            int bg = s * 2 + (t & 1);
#pragma unroll
            for (int nt2 = 0; nt2 < 2; nt2++) {
                uint32_t baddr = sB + (uint32_t)((bn + nt2 * 16) * ROW_B + bg * 16);
                LDSM_X4(bh[nt2], baddr);
                LDSM_X4(bl[nt2], baddr + TILE_B);
            }
            // ---- pass 1: hh (16 independent accumulators) ----
#pragma unroll
            for (int mt = 0; mt < 4; mt++)
#pragma unroll
                for (int nt2 = 0; nt2 < 2; nt2++) {
                    mma16816_f32(acc[mt][nt2 * 2],     ah[mt], bh[nt2]);
                    mma16816_f32(acc[mt][nt2 * 2 + 1], ah[mt], bh[nt2] + 2);
                }
            // ---- pass 2: ah * bl ----
#pragma unroll
            for (int mt = 0; mt < 4; mt++)
#pragma unroll
                for (int nt2 = 0; nt2 < 2; nt2++) {
                    mma16816_f32(acc[mt][nt2 * 2],     ah[mt], bl[nt2]);
                    mma16816_f32(acc[mt][nt2 * 2 + 1], ah[mt], bl[nt2] + 2);
                }
            // ---- pass 3: al * bh ----
#pragma unroll
            for (int mt = 0; mt < 4; mt++)
#pragma unroll
                for (int nt2 = 0; nt2 < 2; nt2++) {
                    mma16816_f32(acc[mt][nt2 * 2],     al[mt], bh[nt2]);
                    mma16816_f32(acc[mt][nt2 * 2 + 1], al[mt], bh[nt2] + 2);
                }
        }
        __syncthreads();
    }

    // ---- fused Matern epilogue ----
    const int r0 = lane >> 2;
    const int c0 = 2 * (lane & 3);
#pragma unroll
    for (int mt = 0; mt < 4; mt++) {
        int row_l = wm * 64 + mt * 16 + r0;
        int row_g = bY * 128 + row_l;
        float sqa0 = s_sq1[row_l];
        float sqa8 = s_sq1[row_l + 8];
        float* orow0 = out + (size_t)row_g * (size_t)n2 + (size_t)bX * 128;
        float* orow8 = orow0 + 8u * (size_t)n2;
#pragma unroll
        for (int nt = 0; nt < 4; nt++) {
            int col_l = wn * 32 + nt * 8 + c0;
            float sqb0 = s_sq2[col_l];
            float sqb1 = s_sq2[col_l + 1];
            const float* a = acc[mt][nt];
            float sqs[4]  = { sqa0 + sqb0, sqa0 + sqb1, sqa8 + sqb0, sqa8 + sqb1 };
            float res[4];
#pragma unroll
            for (int e = 0; e < 4; e++) {
                float d2 = fmaf(-2.f, a[e], sqs[e]);
                d2 = fmaxf(d2, 1e-30f);
                float t = SQRT3F * (d2 * rsqrtf(d2));
                res[e] = (1.f + t) * __expf(-t);
            }
            *reinterpret_cast<float2*>(orow0 + col_l) = make_float2(res[0], res[1]);
            *reinterpret_cast<float2*>(orow8 + col_l) = make_float2(res[2], res[3]);
        }
    }
}

// ============================================================================
// kernel_launch
// ============================================================================
extern "C" void kernel_launch(void* const* d_in, const int* in_sizes, int n_in,
                              void* d_out, int out_size) {
    const float* x1 = (const float*)d_in[0];
    const float* x2 = (const float*)d_in[1];
    const float* ls = (const float*)d_in[2];
    float* out = (float*)d_out;

    int d  = in_sizes[2];            // 256
    int n1 = in_sizes[0] / d;        // 8192
    int n2 = in_sizes[1] / d;        // 8192

    k_mean_partial<<<32, D_DIM>>>(x1, n1);
    k_mean_final<<<1, D_DIM>>>(ls, n1);
    k_normalize2<<<n1 / 8, 256>>>(x1, 0, n1);
    k_normalize2<<<n2 / 8, 256>>>(x2, 1, n2);
    k_spacer<<<1, 32>>>();   // aligns ncu -s 5 -c 1 onto the GEMM launch

    static bool attr_set = false;
    if (!attr_set) {
        cudaFuncSetAttribute(k_matern_gemm,
                             cudaFuncAttributeMaxDynamicSharedMemorySize, SMEM_REQ);
        attr_set = true;
    }
    dim3 grid(n2 / 128, n1 / 128);
    k_matern_gemm<<<grid, 256, SMEM_REQ>>>(out, n2);
}

// round 6
// speedup vs baseline: 1.2422x; 1.0118x over previous
#include <cuda_runtime.h>
#include <cuda_fp16.h>
#include <cstdint>

// ============================================================================
// Problem constants (dataset: n1=n2=8192, d=256)
// ============================================================================
#define D_DIM 256
#define N_MAX 8192
#define SQRT3F 1.7320508075688772f

// Scratch (allocation-free rule: __device__ globals)
__device__ __align__(128) __half g_ah[N_MAX * D_DIM];
__device__ __align__(128) __half g_al[N_MAX * D_DIM];
__device__ __align__(128) __half g_bh[N_MAX * D_DIM];
__device__ __align__(128) __half g_bl[N_MAX * D_DIM];
__device__ __align__(128) float  g_sq1[N_MAX];
__device__ __align__(128) float  g_sq2[N_MAX];
__device__ __align__(128) float  g_part[32 * D_DIM];
__device__ __align__(128) float  g_adj[D_DIM];
__device__ __align__(128) float  g_rls[D_DIM];

__device__ __forceinline__ uint32_t h2_to_u32(__half2 h) {
    union { __half2 h; uint32_t u; } c; c.h = h; return c.u;
}

// ============================================================================
// Portable PTX helpers (sm_80-era ISA only: cp.async / ldmatrix / mma.sync)
// ============================================================================
__device__ __forceinline__ uint32_t smem_u32(const void* p) {
    uint32_t a;
    asm("{ .reg .u64 t; cvta.to.shared.u64 t, %1; cvt.u32.u64 %0, t; }"
        : "=r"(a) : "l"(p));
    return a;
}

__device__ __forceinline__ void cp16(uint32_t dst, const void* src) {
    asm volatile("cp.async.cg.shared.global [%0], [%1], 16;"
                 :: "r"(dst), "l"(src) : "memory");
}
#define CP_COMMIT() asm volatile("cp.async.commit_group;" ::: "memory")
#define CP_WAIT1()  asm volatile("cp.async.wait_group 1;" ::: "memory")

#define LDSM_X4(r, addr) \
    asm volatile("ldmatrix.sync.aligned.m8n8.x4.shared.b16 {%0,%1,%2,%3}, [%4];" \
                 : "=r"((r)[0]), "=r"((r)[1]), "=r"((r)[2]), "=r"((r)[3]) \
                 : "r"(addr))

// fp32-accumulator HMMA
__device__ __forceinline__ void mma16816_f32(float* c, const uint32_t* a,
                                             const uint32_t* b) {
    asm volatile(
        "mma.sync.aligned.m16n8k16.row.col.f32.f16.f16.f32 "
        "{%0,%1,%2,%3}, {%4,%5,%6,%7}, {%8,%9}, {%0,%1,%2,%3};"
        : "+f"(c[0]), "+f"(c[1]), "+f"(c[2]), "+f"(c[3])
        : "r"(a[0]), "r"(a[1]), "r"(a[2]), "r"(a[3]),
          "r"(b[0]), "r"(b[1]));
}

// ============================================================================
// Prep kernels (exactly 3 launches before the GEMM -> ncu -s5 hits the GEMM)
// ============================================================================
__global__ void k_mean_partial(const float* __restrict__ x1, int n1) {
    int d = threadIdx.x, b = blockIdx.x;
    float s = 0.f;
    for (int r = b; r < n1; r += 32) s += x1[(size_t)r * D_DIM + d];
    g_part[b * D_DIM + d] = s;
}

__global__ void k_mean_final(const float* __restrict__ ls, int n1) {
    int d = threadIdx.x;
    float s = 0.f;
#pragma unroll
    for (int b = 0; b < 32; b++) s += g_part[b * D_DIM + d];
    g_adj[d] = s / (float)n1;
    g_rls[d] = 1.0f / ls[d];     // exact divide, once
}

// Center, scale, split fp32 -> fp16 hi + lo; row sqnorm. One warp per row.
// Single launch covers BOTH x1 (rows [0,n1)) and x2 (rows [n1,n1+n2)).
__global__ void k_normalize2(const float* __restrict__ x1,
                             const float* __restrict__ x2, int n1, int ntot) {
    int wid  = threadIdx.x >> 5;
    int lane = threadIdx.x & 31;
    int grow = blockIdx.x * 8 + wid;
    if (grow >= ntot) return;

    int which = (grow >= n1);
    int row   = which ? (grow - n1) : grow;
    const float* x = which ? x2 : x1;
    __half* hi = which ? g_bh : g_ah;
    __half* lo = which ? g_bl : g_al;
    float*  sq = which ? g_sq2 : g_sq1;

    const float4* xr = reinterpret_cast<const float4*>(x + (size_t)row * D_DIM);
    const float4* aj = reinterpret_cast<const float4*>(g_adj);
    const float4* rl = reinterpret_cast<const float4*>(g_rls);

    float ssum = 0.f;
    uint4 packh, packl;
    uint32_t* ph = reinterpret_cast<uint32_t*>(&packh);
    uint32_t* pl = reinterpret_cast<uint32_t*>(&packl);
#pragma unroll
    for (int g = 0; g < 2; g++) {
        int v4 = lane * 2 + g;
        float4 xv = xr[v4];
        float4 av = aj[v4];
        float4 rv = rl[v4];
        float vv[4] = { (xv.x - av.x) * rv.x, (xv.y - av.y) * rv.y,
                        (xv.z - av.z) * rv.z, (xv.w - av.w) * rv.w };
#pragma unroll
        for (int e = 0; e < 4; e += 2) {
            __half h0 = __float2half_rn(vv[e]);
            __half h1 = __float2half_rn(vv[e + 1]);
            __half l0 = __float2half_rn(vv[e] - __half2float(h0));
            __half l1 = __float2half_rn(vv[e + 1] - __half2float(h1));
            ph[g * 2 + e / 2] = h2_to_u32(__halves2half2(h0, h1));
            pl[g * 2 + e / 2] = h2_to_u32(__halves2half2(l0, l1));
            float r0 = __half2float(h0) + __half2float(l0);
            float r1 = __half2float(h1) + __half2float(l1);
            ssum = fmaf(r0, r0, ssum);
            ssum = fmaf(r1, r1, ssum);
        }
    }
    reinterpret_cast<uint4*>(hi + (size_t)row * D_DIM)[lane] = packh;
    reinterpret_cast<uint4*>(lo + (size_t)row * D_DIM)[lane] = packl;
#pragma unroll
    for (int o = 16; o > 0; o >>= 1)
        ssum += __shfl_xor_sync(0xffffffffu, ssum, o);
    if (lane == 0) sq[row] = ssum;
}

// ============================================================================
// Fused GEMM + Matern epilogue (mma.sync m16n8k16, fp16 hi/lo split)
//
// CTA tile 128x128, 4 warps (2x2), warp tile 64x64, occ 2 (8 warps/SM).
// Bigger warp tile halves per-output ldmatrix traffic (smem-crossbar relief).
// K = 256 in 8 chunks of 32, cp.async double-buffered.
// Per k16 step: 96 MMAs in 3 passes (hh / ah*bl / al*bh), 32 independent
// accumulators per pass.
// ============================================================================
#define ROW_B    80                    // padded row stride
#define TILE_B   (128 * ROW_B)         // 10240 B per tile
#define STAGE_B  (4 * TILE_B)          // Ah | Al | Bh | Bl
#define SMEM_REQ (2 * STAGE_B + 1536)

__global__ void __launch_bounds__(128, 2)
k_matern_gemm(float* __restrict__ out, int n2) {
    extern __shared__ char smem_raw[];
    uint32_t sbase_u = smem_u32(smem_raw);
    uint32_t abase = (sbase_u + 127u) & ~127u;
    char* ap = smem_raw + (abase - sbase_u);

    const int tid  = threadIdx.x;
    const int lane = tid & 31;
    const int wid  = tid >> 5;
    const int wm   = wid >> 1;   // 0..1 : 64-row slice
    const int wn   = wid & 1;    // 0..1 : 64-col slice
    const int bX   = blockIdx.x;
    const int bY   = blockIdx.y;

    float* s_sq1 = reinterpret_cast<float*>(ap + 2 * STAGE_B);
    float* s_sq2 = reinterpret_cast<float*>(ap + 2 * STAGE_B + 512);
    s_sq1[tid] = g_sq1[(size_t)bY * 128 + tid];
    s_sq2[tid] = g_sq2[(size_t)bX * 128 + tid];

    const __half* __restrict__ pAh = g_ah + (size_t)bY * 128 * D_DIM;
    const __half* __restrict__ pAl = g_al + (size_t)bY * 128 * D_DIM;
    const __half* __restrict__ pBh = g_bh + (size_t)bX * 128 * D_DIM;
    const __half* __restrict__ pBl = g_bl + (size_t)bX * 128 * D_DIM;

    auto load_stage = [&](int buf, int kc) {
        uint32_t sbuf = abase + (uint32_t)buf * STAGE_B;
        const __half* srcs[4] = { pAh, pAl, pBh, pBl };
#pragma unroll
        for (int t4 = 0; t4 < 4; t4++) {
            const __half* src = srcs[t4];
#pragma unroll
            for (int i = 0; i < 4; i++) {
                int idx = tid + i * 128;            // 0..511
                int row = idx >> 2;                 // 0..127
                int g   = idx & 3;                  // 16B group
                uint32_t daddr = sbuf + (uint32_t)t4 * TILE_B
                               + (uint32_t)(row * ROW_B + g * 16);
                cp16(daddr, src + (size_t)row * D_DIM + kc * 32 + g * 8);
            }
        }
    };

    float acc[4][8][4];                 // [mt 16-row][n8 col][4], fp32
#pragma unroll
    for (int i = 0; i < 4; i++)
#pragma unroll
        for (int j = 0; j < 8; j++)
#pragma unroll
            for (int e = 0; e < 4; e++) acc[i][j][e] = 0.f;

    load_stage(0, 0);
    CP_COMMIT();

    const int NCHUNK = D_DIM / 32;   // 8
    for (int c = 0; c < NCHUNK; c++) {
        if (c + 1 < NCHUNK) load_stage((c + 1) & 1, c + 1);
        CP_COMMIT();
        CP_WAIT1();
        __syncthreads();

        uint32_t sA = abase + (uint32_t)(c & 1) * STAGE_B;
        uint32_t sB = sA + 2 * TILE_B;

#pragma unroll
        for (int s = 0; s < 2; s++) {            // two k16 steps per 32-chunk
            // ---- load ALL fragments (A: 8 LDSM, B: 8 LDSM) ----
            uint32_t ah[4][4], al[4][4], bh[4][4], bl[4][4];
            int arow = wm * 64 + (lane & 15);
            int ag   = s * 2 + (lane >> 4);
#pragma unroll
            for (int mt = 0; mt < 4; mt++) {
                uint32_t aaddr = sA + (uint32_t)((arow + mt * 16) * ROW_B + ag * 16);
                LDSM_X4(ah[mt], aaddr);
                LDSM_X4(al[mt], aaddr + TILE_B);
            }
            int t  = lane >> 3;
            int bn = wn * 64 + ((t >> 1) << 3) + (lane & 7);
            int bg = s * 2 + (t & 1);
#pragma unroll
            for (int ng = 0; ng < 4; ng++) {     // 4 n16 groups = 64 cols
                uint32_t baddr = sB + (uint32_t)((bn + ng * 16) * ROW_B + bg * 16);
                LDSM_X4(bh[ng], baddr);
                LDSM_X4(bl[ng], baddr + TILE_B);
            }
            // ---- pass 1: hh (32 independent accumulators) ----
#pragma unroll
            for (int mt = 0; mt < 4; mt++)
#pragma unroll
                for (int ng = 0; ng < 4; ng++) {
                    mma16816_f32(acc[mt][ng * 2],     ah[mt], bh[ng]);
                    mma16816_f32(acc[mt][ng * 2 + 1], ah[mt], bh[ng] + 2);
                }
            // ---- pass 2: ah * bl ----
#pragma unroll
            for (int mt = 0; mt < 4; mt++)
#pragma unroll
                for (int ng = 0; ng < 4; ng++) {
                    mma16816_f32(acc[mt][ng * 2],     ah[mt], bl[ng]);
                    mma16816_f32(acc[mt][ng * 2 + 1], ah[mt], bl[ng] + 2);
                }
            // ---- pass 3: al * bh ----
#pragma unroll
            for (int mt = 0; mt < 4; mt++)
#pragma unroll
                for (int ng = 0; ng < 4; ng++) {
                    mma16816_f32(acc[mt][ng * 2],     al[mt], bh[ng]);
                    mma16816_f32(acc[mt][ng * 2 + 1], al[mt], bh[ng] + 2);
                }
        }
        __syncthreads();
    }

    // ---- fused Matern epilogue ----
    const int r0 = lane >> 2;
    const int c0 = 2 * (lane & 3);
#pragma unroll
    for (int mt = 0; mt < 4; mt++) {
        int row_l = wm * 64 + mt * 16 + r0;
        int row_g = bY * 128 + row_l;
        float sqa0 = s_sq1[row_l];
        float sqa8 = s_sq1[row_l + 8];
        float* orow0 = out + (size_t)row_g * (size_t)n2 + (size_t)bX * 128;
        float* orow8 = orow0 + 8u * (size_t)n2;
#pragma unroll
        for (int nt = 0; nt < 8; nt++) {
            int col_l = wn * 64 + nt * 8 + c0;
            float sqb0 = s_sq2[col_l];
            float sqb1 = s_sq2[col_l + 1];
            const float* a = acc[mt][nt];
            float sqs[4]  = { sqa0 + sqb0, sqa0 + sqb1, sqa8 + sqb0, sqa8 + sqb1 };
            float res[4];
#pragma unroll
            for (int e = 0; e < 4; e++) {
                float d2 = fmaf(-2.f, a[e], sqs[e]);
                d2 = fmaxf(d2, 1e-30f);
                float t = SQRT3F * (d2 * rsqrtf(d2));
                res[e] = (1.f + t) * __expf(-t);
            }
            *reinterpret_cast<float2*>(orow0 + col_l) = make_float2(res[0], res[1]);
            *reinterpret_cast<float2*>(orow8 + col_l) = make_float2(res[2], res[3]);
        }
    }
}

// ============================================================================
// kernel_launch
// ============================================================================
extern "C" void kernel_launch(void* const* d_in, const int* in_sizes, int n_in,
                              void* d_out, int out_size) {
    const float* x1 = (const float*)d_in[0];
    const float* x2 = (const float*)d_in[1];
    const float* ls = (const float*)d_in[2];
    float* out = (float*)d_out;

    int d  = in_sizes[2];            // 256
    int n1 = in_sizes[0] / d;        // 8192
    int n2 = in_sizes[1] / d;        // 8192

    k_mean_partial<<<32, D_DIM>>>(x1, n1);
    k_mean_final<<<1, D_DIM>>>(ls, n1);
    k_normalize2<<<(n1 + n2) / 8, 256>>>(x1, x2, n1, n1 + n2);

    static bool attr_set = false;
    if (!attr_set) {
        cudaFuncSetAttribute(k_matern_gemm,
                             cudaFuncAttributeMaxDynamicSharedMemorySize, SMEM_REQ);
        attr_set = true;
    }
    dim3 grid(n2 / 128, n1 / 128);
    k_matern_gemm<<<grid, 128, SMEM_REQ>>>(out, n2);
}